// round 14
// baseline (speedup 1.0000x reference)
#include <cuda_runtime.h>
#include <cstdint>
#include <cstddef>

// Problem constants
#define BATCH 8
#define TSEQ  1024
#define DDIM  384
#define DLANG 768
#define HID   512

#define NB   128      // 8 clusters x 16 CTAs
#define NTHR 512
#define GRPB 16       // CTAs per cluster (= per batch group)

// Scratch (allocation-free rule: __device__ globals)
__device__ float g_bufA[BATCH * HID];
__device__ float g_bufB[BATCH * HID];
__device__ float g_f[BATCH * DDIM];

// Dynamic smem layout:
//   float4 tile[6144] : 98304 B (state tile: 64 rows x 96 float4)
//   float  sin[768]   :  3072 B (stage input vector)
//   float  spart[512] :  2048 B (16 kslices x 32 cols)
//   float4 fsh[96]    :  1536 B (f row)
//   uint64 mbar_tile  :     8 B (TMA completion)
//   uint64 pmbar[4]   :    32 B (phase barriers, one per chain sync point)
#define TILE_F4 6144
#define SMEM_BYTES (TILE_F4 * 16 + DLANG * 4 + 512 * 4 + 96 * 16 + 8 + 32 + 8)

extern __shared__ float4 smem_dyn[];

__device__ __forceinline__ uint32_t smem_u32(const void* p) {
    return (uint32_t)__cvta_generic_to_shared(p);
}

__device__ __forceinline__ void mbar_wait_parity0(uint32_t mbar_s) {
    uint32_t done;
    asm volatile(
        "{\n\t.reg .pred p;\n\t"
        "mbarrier.try_wait.parity.acquire.cta.shared::cta.b64 p, [%1], 0;\n\t"
        "selp.b32 %0, 1, 0, p;\n\t}"
        : "=r"(done) : "r"(mbar_s) : "memory");
    if (!done) {
        asm volatile(
            "{\n\t.reg .pred P1;\n\t"
            "WL_%=:\n\t"
            "mbarrier.try_wait.parity.acquire.cta.shared::cta.b64 P1, [%0], 0, 0x989680;\n\t"
            "@P1 bra.uni WD_%=;\n\t"
            "bra.uni WL_%=;\n\t"
            "WD_%=:\n\t}"
            :: "r"(mbar_s) : "memory");
    }
}

// ---------------------------------------------------------------------------
// Cluster phase barrier via DSMEM mbarriers: lanes 0..15 each send one remote
// arrive to peer CTA `lane`; detection is a LOCAL smem mbarrier wait (no L2
// polling). Each phase mbarrier is used once per launch (parity 0, count 16).
// __threadfence() on both sides (with __syncthreads cumulativity) orders the
// stage's global stores against the consumers' loads.
// ---------------------------------------------------------------------------
__device__ __forceinline__ void phase_barrier(uint32_t pmbar_s) {
    __syncthreads();                       // all stage work in this CTA done
    if (threadIdx.x < GRPB) {
        __threadfence();                   // release this CTA's global stores
        uint32_t remote;
        asm volatile("mapa.shared::cluster.u32 %0, %1, %2;"
                     : "=r"(remote) : "r"(pmbar_s), "r"(threadIdx.x));
        asm volatile("mbarrier.arrive.shared::cluster.b64 _, [%0];"
                     :: "r"(remote) : "memory");
    }
    if (threadIdx.x == 0) {
        mbar_wait_parity0(pmbar_s);        // local smem wait (fast path)
        __threadfence();                   // acquire peers' global stores
    }
    __syncthreads();
}

// ---------------------------------------------------------------------------
// One GEMV stage, batch-local: cluster grp (16 CTAs) computes
//   out[grp, :] = in[grp, :] @ W + bias          (W row-major [K, N])
// CTA jt handles cols [jt*32, jt*32+32); jt >= N/32 -> inactive (still
// participates in barriers). Thread (ks, jj): ks = k-slice 0..15, jj = col.
// ---------------------------------------------------------------------------
template <int K, int N>
__device__ __forceinline__ void chain_stage(int grp, int jt,
                                            const float* __restrict__ in,
                                            const float* __restrict__ W,
                                            const float* __restrict__ bias,
                                            float* __restrict__ out,
                                            float* sin, float* spart) {
    constexpr int JT = N / 32;
    constexpr int KW = K / 16;

    for (int i = threadIdx.x; i < K; i += NTHR)
        sin[i] = in[(size_t)grp * K + i];
    __syncthreads();

    if (jt < JT) {
        const int ks = threadIdx.x >> 5;          // 0..15
        const int jj = threadIdx.x & 31;
        const int j  = jt * 32 + jj;
        const float* Wp = W + (size_t)(ks * KW) * N + j;
        const float* sp = sin + ks * KW;
        float acc = 0.0f;
#pragma unroll
        for (int i = 0; i < KW; ++i)
            acc += sp[i] * Wp[(size_t)i * N];
        spart[ks * 32 + jj] = acc;
    }
    __syncthreads();

    if (jt < JT && threadIdx.x < 32) {
        const int j = jt * 32 + threadIdx.x;
        float s = bias[j];
#pragma unroll
        for (int k = 0; k < 16; ++k) s += spart[k * 32 + threadIdx.x];
        out[(size_t)grp * N + j] = s;
    }
    // sin/spart reuse by the next stage is protected by phase_barrier's syncs.
}

// ---------------------------------------------------------------------------
// Fused kernel: 8 independent clusters (one per batch), 16 CTAs each.
//
// Math note: language is broadcast along T, so k/v are identical for all key
// positions; softmax over a constant row is exactly uniform 1/T and ctx == v.
// The Q path and the T x T attention cancel analytically:
//   f[b] = (((language[b] Wv + bv) Wv2 + bv2) Wo + bo) Wout + bout
//   out[b,t,:] = state[b,t,:] + f[b,:]
//
// Sync: DSMEM mbarrier phase barriers (local-smem detection, no L2 polling).
// The 96KB state tile streams on the TMA pipe during the whole chain.
// ---------------------------------------------------------------------------
__global__ void __launch_bounds__(NTHR, 1) __cluster_dims__(GRPB, 1, 1)
fused_cma_kernel(const float* __restrict__ state,
                 const float* __restrict__ language,
                 const float* __restrict__ Wv,  const float* __restrict__ bv,
                 const float* __restrict__ Wv2, const float* __restrict__ bv2,
                 const float* __restrict__ Wo,  const float* __restrict__ bo,
                 const float* __restrict__ Wout,const float* __restrict__ bout,
                 float* __restrict__ out) {
    float4*   tile  = smem_dyn;                              // 6144 float4
    float*    sin   = (float*)(smem_dyn + TILE_F4);          // 768 floats
    float*    spart = sin + DLANG;                           // 512 floats
    float4*   fsh   = (float4*)(spart + 512);                // 96 float4
    uint64_t* mbart = (uint64_t*)(fsh + 96);                 // TMA mbar
    uint64_t* pmbar = mbart + 1;                             // 4 phase mbars

    const int grp = blockIdx.x >> 4;                         // batch / cluster
    const int jt  = blockIdx.x & 15;                         // ctarank in cluster

    const uint32_t mbart_s = smem_u32(mbart);
    const uint32_t pmbar_s = smem_u32(pmbar);
    const uint32_t tile_s  = smem_u32(tile);

    // ---- init mbarriers, then issue the state-tile TMA ----
    const int t0 = jt * 64;                                  // row start
    const size_t base = ((size_t)grp * TSEQ + t0) * DDIM;

    if (threadIdx.x == 0) {
        asm volatile("mbarrier.init.shared.b64 [%0], 1;" :: "r"(mbart_s) : "memory");
#pragma unroll
        for (int ph = 0; ph < 4; ++ph)
            asm volatile("mbarrier.init.shared.b64 [%0], %1;"
                         :: "r"(pmbar_s + 8u * ph), "r"(GRPB) : "memory");
        asm volatile("fence.proxy.async.shared::cta;" ::: "memory");
        asm volatile("mbarrier.arrive.expect_tx.shared.b64 _, [%0], %1;"
                     :: "r"(mbart_s), "r"((unsigned)(TILE_F4 * 16)) : "memory");
        asm volatile(
            "cp.async.bulk.shared::cta.global.mbarrier::complete_tx::bytes "
            "[%0], [%1], %2, [%3];"
            :: "r"(tile_s), "l"(state + base), "r"((unsigned)(TILE_F4 * 16)),
               "r"(mbart_s) : "memory");
    }

    // Cluster sync: all CTAs' phase mbarriers initialized before any remote
    // arrive can target them.
    asm volatile("barrier.cluster.arrive.aligned;" ::: "memory");
    asm volatile("barrier.cluster.wait.aligned;" ::: "memory");

    // ---- GEMV chain, batch-local (DSMEM phase barriers) ----
    chain_stage<DLANG, HID>(grp, jt, language, Wv,   bv,   g_bufA, sin, spart);
    phase_barrier(pmbar_s + 0);
    chain_stage<HID,   HID>(grp, jt, g_bufA,   Wv2,  bv2,  g_bufB, sin, spart);
    phase_barrier(pmbar_s + 8);
    chain_stage<HID,   HID>(grp, jt, g_bufB,   Wo,   bo,   g_bufA, sin, spart);
    phase_barrier(pmbar_s + 16);
    chain_stage<HID,  DDIM>(grp, jt, g_bufA,   Wout, bout, g_f,    sin, spart);
    phase_barrier(pmbar_s + 24);                             // f[grp] ready

    // ---- f row into smem ----
    if (threadIdx.x < DDIM / 4) {
        fsh[threadIdx.x] =
            ((const float4*)(g_f + (size_t)grp * DDIM))[threadIdx.x];
    }
    __syncthreads();

    // Register-resident f: p = tid + it*512; 512 mod 96 = 32 -> period 3.
    const int dq0 = threadIdx.x % (DDIM / 4);
    const float4 f0 = fsh[dq0];
    const float4 f1 = fsh[(dq0 + 32) % (DDIM / 4)];
    const float4 f2 = fsh[(dq0 + 64) % (DDIM / 4)];

    // ---- Wait for the state tile ----
    mbar_wait_parity0(mbart_s);

    // ---- Residual add + store: 6144 float4 per block, 12 per thread ----
    float4* op = (float4*)(out + base);
#pragma unroll
    for (int it = 0; it < 12; ++it) {
        const int p = threadIdx.x + it * NTHR;
        float4 s = tile[p];
        const float4 fv = (it % 3 == 0) ? f0 : ((it % 3 == 1) ? f1 : f2);
        s.x += fv.x; s.y += fv.y; s.z += fv.z; s.w += fv.w;
        op[p] = s;
    }

    // No trailing cluster sync needed: the only cross-CTA smem traffic is the
    // phase-barrier arrivals, all of which completed before phase_barrier 3's
    // local wait released this CTA... but a peer may still be arriving at OUR
    // phase mbar? No: our phase-3 wait saw all 16 arrivals; earlier-phase
    // arrivals are also all complete (they precede peers' phase-3 arrivals).
    // Cluster teardown is therefore safe.
}

// ---------------------------------------------------------------------------
// Inputs (metadata order):
//  0 state [B,T,D]   1 language [B,DL]
//  2 Wq 3 bq 4 Wk 5 bk 6 Wv 7 bv
//  8 Wq2 9 bq2 10 Wk2 11 bk2 12 Wv2 13 bv2
// 14 Wo 15 bo 16 Wout 17 bout
// Output: float32 [B,T,D]
// ---------------------------------------------------------------------------
extern "C" void kernel_launch(void* const* d_in, const int* in_sizes, int n_in,
                              void* d_out, int out_size) {
    (void)in_sizes; (void)n_in; (void)out_size;

    const float* state    = (const float*)d_in[0];
    const float* language = (const float*)d_in[1];
    const float* Wv   = (const float*)d_in[6];
    const float* bv   = (const float*)d_in[7];
    const float* Wv2  = (const float*)d_in[12];
    const float* bv2  = (const float*)d_in[13];
    const float* Wo   = (const float*)d_in[14];
    const float* bo   = (const float*)d_in[15];
    const float* Wout = (const float*)d_in[16];
    const float* bout = (const float*)d_in[17];
    float* out = (float*)d_out;

    cudaFuncSetAttribute(fused_cma_kernel,
                         cudaFuncAttributeMaxDynamicSharedMemorySize,
                         SMEM_BYTES);
    // 16-CTA clusters exceed the portable limit of 8.
    cudaFuncSetAttribute(fused_cma_kernel,
                         cudaFuncAttributeNonPortableClusterSizeAllowed, 1);

    fused_cma_kernel<<<NB, NTHR, SMEM_BYTES>>>(state, language,
                                               Wv, bv, Wv2, bv2, Wo, bo,
                                               Wout, bout, out);
}

// round 15
// speedup vs baseline: 1.4180x; 1.4180x over previous
#include <cuda_runtime.h>
#include <cstdint>
#include <cstddef>

// Problem constants
#define BATCH 8
#define TSEQ  1024
#define DDIM  384
#define DLANG 768
#define HID   512

#define NB     128    // chain kernel: 8 groups x 16 blocks, one wave
#define NTHR_A 512
#define GRPB   16

// Scratch + barrier state (allocation-free rule: __device__ globals)
__device__ float g_bufA[BATCH * HID];
__device__ float g_bufB[BATCH * HID];
__device__ float g_f[BATCH * DDIM];
__device__ unsigned g_gbar[BATCH][4];   // per-group monotonic tickets; never reset

// ---------------------------------------------------------------------------
// Per-group (16-block) ticket barrier: monotonic, no reset across replays.
// All 16 blocks of a group arrive at every phase (inactive jt too), so each
// counter is a clean multiple of 16 at phase entry of every launch/replay.
// ---------------------------------------------------------------------------
__device__ __forceinline__ void group_barrier(int grp, int phase) {
    __syncthreads();
    if (threadIdx.x == 0) {
        __threadfence();
        const unsigned old = atomicAdd(&g_gbar[grp][phase], 1u);
        const unsigned target = old - (old & (GRPB - 1)) + GRPB;
        volatile unsigned* p = &g_gbar[grp][phase];
        while ((int)(*p - target) < 0) { __nanosleep(16); }
        __threadfence();
    }
    __syncthreads();
}

// ---------------------------------------------------------------------------
// One GEMV stage, batch-local: group grp (16 blocks) computes
//   out[grp, :] = in[grp, :] @ W + bias          (W row-major [K, N])
// Block jt handles cols [jt*32, jt*32+32); jt >= N/32 -> inactive (still
// participates in barriers). Thread (ks, jj): ks = k-slice 0..15, jj = col.
// Weight loads: 32 consecutive j per warp -> fully coalesced 128B lines.
// ---------------------------------------------------------------------------
template <int K, int N>
__device__ __forceinline__ void chain_stage(int grp, int jt,
                                            const float* __restrict__ in,
                                            const float* __restrict__ W,
                                            const float* __restrict__ bias,
                                            float* __restrict__ out,
                                            float* sin, float* spart) {
    constexpr int JT = N / 32;
    constexpr int KW = K / 16;

    for (int i = threadIdx.x; i < K; i += NTHR_A)
        sin[i] = in[(size_t)grp * K + i];
    __syncthreads();

    if (jt < JT) {
        const int ks = threadIdx.x >> 5;          // 0..15
        const int jj = threadIdx.x & 31;
        const int j  = jt * 32 + jj;
        const float* Wp = W + (size_t)(ks * KW) * N + j;
        const float* sp = sin + ks * KW;
        float acc = 0.0f;
#pragma unroll
        for (int i = 0; i < KW; ++i)
            acc += sp[i] * Wp[(size_t)i * N];
        spart[ks * 32 + jj] = acc;
    }
    __syncthreads();

    if (jt < JT && threadIdx.x < 32) {
        const int j = jt * 32 + threadIdx.x;
        float s = bias[j];
#pragma unroll
        for (int k = 0; k < 16; ++k) s += spart[k * 32 + threadIdx.x];
        out[(size_t)grp * N + j] = s;
    }
    // sin/spart reuse by the next stage is protected by group_barrier's syncs.
}

// ---------------------------------------------------------------------------
// Kernel A: batch-diagonal GEMV chain (8 independent 16-block groups, only
// per-group barriers). Triggers PDL at entry so the residual kernel
// co-schedules and streams `state` while this runs. Final stage writes the
// dense f row; the kernel boundary is the producer-consumer sync.
//
// Math note: language is broadcast along T, so k/v are identical for all key
// positions; softmax over a constant row is exactly uniform 1/T and ctx == v.
// The Q path and the T x T attention cancel analytically:
//   f[b] = (((language[b] Wv + bv) Wv2 + bv2) Wo + bo) Wout + bout
//   out[b,t,:] = state[b,t,:] + f[b,:]
// ---------------------------------------------------------------------------
__global__ void __launch_bounds__(NTHR_A, 1)
chain_kernel(const float* __restrict__ language,
             const float* __restrict__ Wv,  const float* __restrict__ bv,
             const float* __restrict__ Wv2, const float* __restrict__ bv2,
             const float* __restrict__ Wo,  const float* __restrict__ bo,
             const float* __restrict__ Wout,const float* __restrict__ bout) {
    if (threadIdx.x == 0) cudaTriggerProgrammaticLaunchCompletion();

    __shared__ float sin[DLANG];
    __shared__ float spart[512];

    const int grp = blockIdx.x >> 4;
    const int jt  = blockIdx.x & 15;

    chain_stage<DLANG, HID>(grp, jt, language, Wv,   bv,   g_bufA, sin, spart);
    group_barrier(grp, 0);
    chain_stage<HID,   HID>(grp, jt, g_bufA,   Wv2,  bv2,  g_bufB, sin, spart);
    group_barrier(grp, 1);
    chain_stage<HID,   HID>(grp, jt, g_bufB,   Wo,   bo,   g_bufA, sin, spart);
    group_barrier(grp, 2);
    chain_stage<HID,  DDIM>(grp, jt, g_bufA,   Wout, bout, g_f,    sin, spart);
}

// ---------------------------------------------------------------------------
// Kernel B: residual broadcast add. PDL: co-schedules with kernel A, loads
// its state tile into registers DURING the chain, then grid-dep-syncs, reads
// the dense f row, adds, stores.
// Grid (64, 8): 512 blocks x 256 thr, 16 rows of 384 floats per block.
// ---------------------------------------------------------------------------
__global__ void __launch_bounds__(256)
residual_kernel(const float* __restrict__ state, float* __restrict__ out) {
    const int b  = blockIdx.y;
    const int t0 = blockIdx.x * 16;
    const size_t base = ((size_t)b * TSEQ + t0) * DDIM;
    const float4* sp = (const float4*)(state + base);

    // 16 rows * 96 float4 = 1536 float4 -> 6 per thread, loaded pre-sync.
    float4 s0 = sp[threadIdx.x + 0 * 256];
    float4 s1 = sp[threadIdx.x + 1 * 256];
    float4 s2 = sp[threadIdx.x + 2 * 256];
    float4 s3 = sp[threadIdx.x + 3 * 256];
    float4 s4 = sp[threadIdx.x + 4 * 256];
    float4 s5 = sp[threadIdx.x + 5 * 256];

    // Wait for the chain kernel's f to be visible.
    cudaGridDependencySynchronize();

    __shared__ float4 fsh[DDIM / 4];   // 96
    if (threadIdx.x < DDIM / 4) {
        fsh[threadIdx.x] =
            ((const float4*)(g_f + (size_t)b * DDIM))[threadIdx.x];
    }
    __syncthreads();

    // p = tid + it*256; p mod 96 cycles {dq0, dq0+64, dq0+32} (256 mod 96 = 64).
    const int dq0 = threadIdx.x % (DDIM / 4);
    const float4 f0 = fsh[dq0];
    const float4 f1 = fsh[(dq0 + 64) % (DDIM / 4)];
    const float4 f2 = fsh[(dq0 + 32) % (DDIM / 4)];

    float4* op = (float4*)(out + base);
    s0.x += f0.x; s0.y += f0.y; s0.z += f0.z; s0.w += f0.w; op[threadIdx.x + 0*256] = s0;
    s1.x += f1.x; s1.y += f1.y; s1.z += f1.z; s1.w += f1.w; op[threadIdx.x + 1*256] = s1;
    s2.x += f2.x; s2.y += f2.y; s2.z += f2.z; s2.w += f2.w; op[threadIdx.x + 2*256] = s2;
    s3.x += f0.x; s3.y += f0.y; s3.z += f0.z; s3.w += f0.w; op[threadIdx.x + 3*256] = s3;
    s4.x += f1.x; s4.y += f1.y; s4.z += f1.z; s4.w += f1.w; op[threadIdx.x + 4*256] = s4;
    s5.x += f2.x; s5.y += f2.y; s5.z += f2.z; s5.w += f2.w; op[threadIdx.x + 5*256] = s5;
}

// ---------------------------------------------------------------------------
// Inputs (metadata order):
//  0 state [B,T,D]   1 language [B,DL]
//  2 Wq 3 bq 4 Wk 5 bk 6 Wv 7 bv
//  8 Wq2 9 bq2 10 Wk2 11 bk2 12 Wv2 13 bv2
// 14 Wo 15 bo 16 Wout 17 bout
// Output: float32 [B,T,D]
// ---------------------------------------------------------------------------
extern "C" void kernel_launch(void* const* d_in, const int* in_sizes, int n_in,
                              void* d_out, int out_size) {
    (void)in_sizes; (void)n_in; (void)out_size;

    const float* state    = (const float*)d_in[0];
    const float* language = (const float*)d_in[1];
    const float* Wv   = (const float*)d_in[6];
    const float* bv   = (const float*)d_in[7];
    const float* Wv2  = (const float*)d_in[12];
    const float* bv2  = (const float*)d_in[13];
    const float* Wo   = (const float*)d_in[14];
    const float* bo   = (const float*)d_in[15];
    const float* Wout = (const float*)d_in[16];
    const float* bout = (const float*)d_in[17];
    float* out = (float*)d_out;

    // Kernel A: batch-diagonal GEMV chain (ticket barriers -> no reset node).
    chain_kernel<<<NB, NTHR_A>>>(language, Wv, bv, Wv2, bv2, Wo, bo,
                                 Wout, bout);

    // Kernel B: residual add, PDL so it co-schedules with A and streams
    // `state` while the chain runs.
    cudaLaunchConfig_t cfg = {};
    cfg.gridDim  = dim3(TSEQ / 16, BATCH, 1);
    cfg.blockDim = dim3(256, 1, 1);
    cfg.dynamicSmemBytes = 0;
    cfg.stream = 0;
    cudaLaunchAttribute attrs[1];
    attrs[0].id = cudaLaunchAttributeProgrammaticStreamSerialization;
    attrs[0].val.programmaticStreamSerializationAllowed = 1;
    cfg.attrs = attrs;
    cfg.numAttrs = 1;
    cudaLaunchKernelEx(&cfg, residual_kernel, state, out);
}